// round 10
// baseline (speedup 1.0000x reference)
#include <cuda_runtime.h>

#define NB 4
#define NA 100000
#define NM 32
#define NC 80
#define TPB 256
#define NCHUNK_X ((NA + TPB - 1) / TPB)   // 391 chunks per image
#define NCHUNKS (NCHUNK_X * NB)           // 1564 = 2 * 782
#define GRID (NCHUNKS / 2)                // 782 blocks, 2 chunks each
#define NEG_W (-0.51986038543f)           /* -0.75 * ln(2) */
#define POS_W (-0.17328679514f)           /* -0.25 * ln(2) */
#define PMAX (1.0f - 1.0e-4f)
#define FULL 0xffffffffu

// [0]=cls_sum, [1]=reg_sum, [2]=num_pos  (zero-init; reset by finalizer block)
__device__ double g_acc[3];
__device__ unsigned int g_count;

__device__ __forceinline__ float warp_sum(float v) {
    #pragma unroll
    for (int o = 16; o > 0; o >>= 1) v += __shfl_down_sync(FULL, v, o);
    return v;
}

__device__ __forceinline__ float huber(float x) {
    float d = fabsf(x);
    return (d < (1.0f / 9.0f)) ? 4.5f * d * d : d - (0.5f / 9.0f);
}

// negative-class focal term (weight applied by caller)
__device__ __forceinline__ float nt(float p) {
    float pu = fminf(p, PMAX);
    return pu * pu * __log2f(1.0f - pu);
}

__device__ __forceinline__ float sum4(float4 v) {
    return (nt(v.x) + nt(v.y)) + (nt(v.z) + nt(v.w));
}

__global__ __launch_bounds__(TPB, 6) void fused_loss_kernel(
    const float*  __restrict__ cls_f,      // (B, A, 80)
    const float4* __restrict__ regression, // (B, A)
    const float4* __restrict__ anchors,    // (A)
    const float*  __restrict__ annotations,// (B, M, 5)
    float* __restrict__ out)
{
    __shared__ float4 sb4[NB * NM];    // all 4 images' box coords
    __shared__ float  sarea[NB * NM];  // areas
    __shared__ float  scls[NB * NM];   // classes
    __shared__ float  sred[24];

    const int tid  = threadIdx.x;
    const int lane = tid & 31;
    const int wrp  = tid >> 5;

    // ---- one-time: load ALL annotations (4 images x 32 boxes) ----
    if (tid < NB * NM) {
        const float* ap = annotations + tid * 5;
        float x1 = ap[0], y1 = ap[1], x2 = ap[2], y2 = ap[3];
        sb4[tid]   = make_float4(x1, y1, x2, y2);
        sarea[tid] = (x2 - x1) * (y2 - y1);
        scls[tid]  = ap[4];
    }
    __syncthreads();

    float cls_acc = 0.0f, reg_acc = 0.0f, pos_acc = 0.0f;

    // ---- static persistent: block handles chunks bid and bid+GRID ----
    #pragma unroll
    for (int half = 0; half < 2; half++) {
        const int t  = blockIdx.x + half * GRID;
        const int b  = t / NCHUNK_X;
        const int a0 = (t - b * NCHUNK_X) * TPB;
        const int warp_a0 = a0 + wrp * 32;
        const int a  = warp_a0 + lane;
        const int bm = b * NM;
        const bool wactive = (warp_a0 < NA);   // tail warp-aligned (160 = 5*32)

        if (!wactive) continue;

        // ---- Phase A: per-thread IoU argmax (division-free) ----
        float4 an = anchors[a];
        float area_a = (an.z - an.x) * (an.w - an.y);
        float ib = -1.0f, ub = 1.0f;
        int best = 0;
        #pragma unroll
        for (int m = 0; m < NM; m++) {
            float4 bx = sb4[bm + m];
            float iw = fminf(an.z, bx.z) - fmaxf(an.x, bx.x);
            float ih = fminf(an.w, bx.w) - fmaxf(an.y, bx.y);
            float inter = fmaxf(iw, 0.0f) * fmaxf(ih, 0.0f);
            float uni = area_a + sarea[bm + m] - inter;
            if (inter * ub > ib * uni) { ib = inter; ub = uni; best = m; }
        }
        float best_iou = ib / fmaxf(ub, 1e-8f);
        bool pos = best_iou >= 0.5f;
        bool ign = (best_iou > 0.4f) && !pos;
        float cx = (an.x + an.z) * 0.5f;
        float cy = (an.y + an.w) * 0.5f;
        bool inside = (cx >= 0.0f) && (cx < 800.0f) && (cy >= 0.0f) && (cy < 800.0f);
        bool valid = inside && !ign;
        bool is_pos = inside && pos;
        float w = valid ? NEG_W : 0.0f;

        // ---- Phase B: warp-cooperative coalesced stream (640 float4s) ----
        {
            const float4* slab = (const float4*)cls_f + ((size_t)b * NA + warp_a0) * 20;
            float acc = 0.0f;
            #pragma unroll
            for (int k0 = 0; k0 < 20; k0 += 4) {
                const unsigned i0 = lane + 32 * k0;
                const unsigned i1 = i0 + 32, i2 = i0 + 64, i3 = i0 + 96;
                float4 v0 = __ldcs(slab + i0);
                float4 v1 = __ldcs(slab + i1);
                float4 v2 = __ldcs(slab + i2);
                float4 v3 = __ldcs(slab + i3);
                float w0 = __shfl_sync(FULL, w, i0 / 20u);
                float w1 = __shfl_sync(FULL, w, i1 / 20u);
                float w2 = __shfl_sync(FULL, w, i2 / 20u);
                float w3 = __shfl_sync(FULL, w, i3 / 20u);
                acc = fmaf(sum4(v0), w0, acc);
                acc = fmaf(sum4(v1), w1, acc);
                acc = fmaf(sum4(v2), w2, acc);
                acc = fmaf(sum4(v3), w3, acc);
            }
            cls_acc += acc;
        }

        // ---- positive-anchor extras (rare path) ----
        if (is_pos) {
            pos_acc += 1.0f;
            float4 bx = sb4[bm + best];
            float aw = an.z - an.x, ah = an.w - an.y;
            float t0 = ((bx.x - an.x) / aw) * 5.0f;
            float t1 = ((bx.y - an.y) / ah) * 5.0f;
            float t2 = ((bx.z - an.z) / aw) * 5.0f;
            float t3 = ((bx.w - an.w) / ah) * 5.0f;
            float4 r = regression[(size_t)b * NA + a];
            reg_acc += huber(r.x - t0) + huber(r.y - t1) + huber(r.z - t2) + huber(r.w - t3);

            // correction: + true positive-label term, − the negative term added above
            int lc = (int)scls[bm + best];
            float p = cls_f[((size_t)b * NA + a) * NC + lc];
            float pc = fminf(fmaxf(p, 1.0e-4f), PMAX);
            float q = 1.0f - pc;
            cls_acc += POS_W * q * q * __log2f(pc) - NEG_W * nt(p);
        }
    }

    // ---- final block reduce (8 warps), 3 double atomics, last-block finalize ----
    float wc = warp_sum(cls_acc);
    float wr = warp_sum(reg_acc);
    float wp = warp_sum(pos_acc);
    if (lane == 0) { sred[wrp] = wc; sred[8 + wrp] = wr; sred[16 + wrp] = wp; }
    __syncthreads();
    if (wrp == 0) {
        float vc = (lane < 8) ? sred[lane] : 0.0f;
        float vr = (lane < 8) ? sred[8 + lane] : 0.0f;
        float vp = (lane < 8) ? sred[16 + lane] : 0.0f;
        vc = warp_sum(vc); vr = warp_sum(vr); vp = warp_sum(vp);
        if (lane == 0) {
            atomicAdd(&g_acc[0], (double)vc);
            if (vr != 0.0f) atomicAdd(&g_acc[1], (double)vr);
            if (vp != 0.0f) atomicAdd(&g_acc[2], (double)vp);
            __threadfence();
            unsigned int done = atomicAdd(&g_count, 1u);
            if (done == GRID - 1) {
                double np = g_acc[2];
                if (np < 1.0) np = 1.0;
                out[0] = (float)((g_acc[0] + g_acc[1]) / np);
                g_acc[0] = 0.0; g_acc[1] = 0.0; g_acc[2] = 0.0;
                __threadfence();
                g_count = 0u;
            }
        }
    }
}

extern "C" void kernel_launch(void* const* d_in, const int* in_sizes, int n_in,
                              void* d_out, int out_size) {
    const float* cls = (const float*)d_in[0];  // (B, A, 80)
    const float* reg = (const float*)d_in[1];  // (B, A, 4)
    const float* anc = (const float*)d_in[2];  // (A, 4)
    const float* ann = (const float*)d_in[3];  // (B, M, 5)

    fused_loss_kernel<<<GRID, TPB>>>(
        cls, (const float4*)reg, (const float4*)anc, ann, (float*)d_out);
}

// round 11
// speedup vs baseline: 1.1441x; 1.1441x over previous
#include <cuda_runtime.h>

#define NB 4
#define NA 100000
#define NM 32
#define NC 80
#define TPB 256
#define NBLK_X ((NA + TPB - 1) / TPB)     // 391
#define TOTAL_BLOCKS (NBLK_X * NB)        // 1564
#define NEG_W (-0.51986038543f)           /* -0.75 * ln(2) */
#define POS_W (-0.17328679514f)           /* -0.25 * ln(2) */
#define PMAX (1.0f - 1.0e-4f)
#define FULL 0xffffffffu

// [0]=cls_sum, [1]=reg_sum, [2]=num_pos  (zero-init; reset by finalizer block)
__device__ double g_acc[3];
__device__ unsigned int g_count;

__device__ __forceinline__ float warp_sum(float v) {
    #pragma unroll
    for (int o = 16; o > 0; o >>= 1) v += __shfl_down_sync(FULL, v, o);
    return v;
}

__device__ __forceinline__ float huber(float x) {
    float d = fabsf(x);
    return (d < (1.0f / 9.0f)) ? 4.5f * d * d : d - (0.5f / 9.0f);
}

// negative-class focal term (weight applied by caller)
__device__ __forceinline__ float nt(float p) {
    float pu = fminf(p, PMAX);
    return pu * pu * __log2f(1.0f - pu);
}

__device__ __forceinline__ float sum4(float4 v) {
    return (nt(v.x) + nt(v.y)) + (nt(v.z) + nt(v.w));
}

__global__ __launch_bounds__(TPB) void fused_loss_kernel(
    const float*  __restrict__ cls_f,      // (B, A, 80)
    const float4* __restrict__ regression, // (B, A)
    const float4* __restrict__ anchors,    // (A)
    const float*  __restrict__ annotations,// (B, M, 5)
    float* __restrict__ out)
{
    __shared__ float4 sb4[NM];    // box coords
    __shared__ float  sarea[NM];  // box areas
    __shared__ float  scls[NM];   // box classes
    __shared__ float  sred[24];

    const int b    = blockIdx.y;
    const int tid  = threadIdx.x;
    const int lane = tid & 31;
    const int wrp  = tid >> 5;
    const int warp_a0 = blockIdx.x * TPB + wrp * 32;
    const int a    = warp_a0 + lane;
    const bool wactive = (warp_a0 < NA);   // tail warp-aligned (160 = 5*32)

    // ---- prefetch: anchor + first cls batch issued BEFORE the barrier ----
    float4 an = make_float4(0.f, 0.f, 0.f, 0.f);
    float4 c0, c1, c2, c3;
    const float4* slab = (const float4*)cls_f;
    if (wactive) {
        an   = anchors[a];
        slab = (const float4*)cls_f + ((size_t)b * NA + warp_a0) * 20;
        c0 = __ldcs(slab + lane);
        c1 = __ldcs(slab + lane + 32);
        c2 = __ldcs(slab + lane + 64);
        c3 = __ldcs(slab + lane + 96);
    }

    if (tid < NM) {
        const float* ap = annotations + (b * NM + tid) * 5;
        float x1 = ap[0], y1 = ap[1], x2 = ap[2], y2 = ap[3];
        sb4[tid]   = make_float4(x1, y1, x2, y2);
        sarea[tid] = (x2 - x1) * (y2 - y1);
        scls[tid]  = ap[4];
    }
    __syncthreads();

    float cls_acc = 0.0f, reg_acc = 0.0f, pos_acc = 0.0f;

    if (wactive) {
        // ---- Phase A: per-thread IoU argmax (division-free) ----
        float area_a = (an.z - an.x) * (an.w - an.y);
        float ib = -1.0f, ub = 1.0f;
        int best = 0;
        #pragma unroll
        for (int m = 0; m < NM; m++) {
            float4 bx = sb4[m];
            float iw = fminf(an.z, bx.z) - fmaxf(an.x, bx.x);
            float ih = fminf(an.w, bx.w) - fmaxf(an.y, bx.y);
            float inter = fmaxf(iw, 0.0f) * fmaxf(ih, 0.0f);
            float uni = area_a + sarea[m] - inter;
            if (inter * ub > ib * uni) { ib = inter; ub = uni; best = m; }
        }
        float best_iou = ib / fmaxf(ub, 1e-8f);
        bool pos = best_iou >= 0.5f;
        bool ign = (best_iou > 0.4f) && !pos;
        float cx = (an.x + an.z) * 0.5f;
        float cy = (an.y + an.w) * 0.5f;
        bool inside = (cx >= 0.0f) && (cx < 800.0f) && (cy >= 0.0f) && (cy < 800.0f);
        bool valid = inside && !ign;
        bool is_pos = inside && pos;
        float w = valid ? NEG_W : 0.0f;

        // ---- Phase B: double-buffered coalesced stream (640 float4s/warp) ----
        float acc = 0.0f;
        #pragma unroll
        for (int k0 = 0; k0 < 20; k0 += 4) {
            float4 n0, n1, n2, n3;
            if (k0 + 4 < 20) {
                // prefetch next batch before touching current one
                n0 = __ldcs(slab + lane + 32 * (k0 + 4));
                n1 = __ldcs(slab + lane + 32 * (k0 + 5));
                n2 = __ldcs(slab + lane + 32 * (k0 + 6));
                n3 = __ldcs(slab + lane + 32 * (k0 + 7));
            }
            const unsigned i0 = lane + 32 * k0;
            float w0 = __shfl_sync(FULL, w, i0 / 20u);
            float w1 = __shfl_sync(FULL, w, (i0 + 32) / 20u);
            float w2 = __shfl_sync(FULL, w, (i0 + 64) / 20u);
            float w3 = __shfl_sync(FULL, w, (i0 + 96) / 20u);
            acc = fmaf(sum4(c0), w0, acc);
            acc = fmaf(sum4(c1), w1, acc);
            acc = fmaf(sum4(c2), w2, acc);
            acc = fmaf(sum4(c3), w3, acc);
            if (k0 + 4 < 20) { c0 = n0; c1 = n1; c2 = n2; c3 = n3; }
        }
        cls_acc = acc;

        // ---- positive-anchor extras (rare path) ----
        if (is_pos) {
            pos_acc = 1.0f;
            float4 bx = sb4[best];
            float aw = an.z - an.x, ah = an.w - an.y;
            float t0 = ((bx.x - an.x) / aw) * 5.0f;
            float t1 = ((bx.y - an.y) / ah) * 5.0f;
            float t2 = ((bx.z - an.z) / aw) * 5.0f;
            float t3 = ((bx.w - an.w) / ah) * 5.0f;
            float4 r = regression[(size_t)b * NA + a];
            reg_acc = huber(r.x - t0) + huber(r.y - t1) + huber(r.z - t2) + huber(r.w - t3);

            // correction: + true positive-label term, − the negative term added above
            int lc = (int)scls[best];
            float p = cls_f[((size_t)b * NA + a) * NC + lc];
            float pc = fminf(fmaxf(p, 1.0e-4f), PMAX);
            float q = 1.0f - pc;
            cls_acc += POS_W * q * q * __log2f(pc) - NEG_W * nt(p);
        }
    }

    // ---- Phase C: block reduce (8 warps), 3 double atomics, last-block finalize ----
    float wc = warp_sum(cls_acc);
    float wr = warp_sum(reg_acc);
    float wp = warp_sum(pos_acc);
    if (lane == 0) { sred[wrp] = wc; sred[8 + wrp] = wr; sred[16 + wrp] = wp; }
    __syncthreads();
    if (wrp == 0) {
        float vc = (lane < 8) ? sred[lane] : 0.0f;
        float vr = (lane < 8) ? sred[8 + lane] : 0.0f;
        float vp = (lane < 8) ? sred[16 + lane] : 0.0f;
        vc = warp_sum(vc); vr = warp_sum(vr); vp = warp_sum(vp);
        if (lane == 0) {
            atomicAdd(&g_acc[0], (double)vc);
            if (vr != 0.0f) atomicAdd(&g_acc[1], (double)vr);
            if (vp != 0.0f) atomicAdd(&g_acc[2], (double)vp);
            __threadfence();
            unsigned int done = atomicAdd(&g_count, 1u);
            if (done == TOTAL_BLOCKS - 1) {
                double np = g_acc[2];
                if (np < 1.0) np = 1.0;
                out[0] = (float)((g_acc[0] + g_acc[1]) / np);
                g_acc[0] = 0.0; g_acc[1] = 0.0; g_acc[2] = 0.0;
                __threadfence();
                g_count = 0u;
            }
        }
    }
}

extern "C" void kernel_launch(void* const* d_in, const int* in_sizes, int n_in,
                              void* d_out, int out_size) {
    const float* cls = (const float*)d_in[0];  // (B, A, 80)
    const float* reg = (const float*)d_in[1];  // (B, A, 4)
    const float* anc = (const float*)d_in[2];  // (A, 4)
    const float* ann = (const float*)d_in[3];  // (B, M, 5)

    dim3 grid(NBLK_X, NB);
    fused_loss_kernel<<<grid, TPB>>>(
        cls, (const float4*)reg, (const float4*)anc, ann, (float*)d_out);
}